// round 3
// baseline (speedup 1.0000x reference)
#include <cuda_runtime.h>

#define S_ 64
#define B_ 64
#define H_ 512
#define E_ 512
#define L_ 2
#define V_ 32000
#define K_ (E_ + H_)   // 1024

// ---------------- device scratch (no allocations allowed) ----------------
__device__ __align__(16) float g_x[S_ * B_ * E_];      // embedded inputs, 8 MB
__device__ __align__(16) float g_hall[S_ * B_ * H_];   // last-layer hidden per step, 8 MB
__device__ __align__(16) float g_hA[L_ * B_ * H_];     // ping-pong hidden buffers
__device__ __align__(16) float g_hB[L_ * B_ * H_];
__device__ __align__(16) float g_rz[B_ * K_];          // r (j<512) and z (j>=512) gates

// ---------------- packed fp32x2 helpers (Blackwell FFMA2 path) ----------------
__device__ __forceinline__ unsigned long long pack2(float lo, float hi) {
    unsigned long long r;
    asm("mov.b64 %0, {%1, %2};" : "=l"(r) : "f"(lo), "f"(hi));
    return r;
}
__device__ __forceinline__ void ffma2(unsigned long long& d,
                                      unsigned long long a,
                                      unsigned long long b) {
    asm("fma.rn.f32x2 %0, %1, %2, %0;" : "+l"(d) : "l"(a), "l"(b));
}
__device__ __forceinline__ float2 unpack2(unsigned long long v) {
    float lo, hi;
    asm("mov.b64 {%0, %1}, %2;" : "=f"(lo), "=f"(hi) : "l"(v));
    return make_float2(lo, hi);
}

// ---------------- embedding gather ----------------
__global__ void embed_kernel(const int* __restrict__ tokens,
                             const float* __restrict__ emb) {
    int idx = blockIdx.x * blockDim.x + threadIdx.x;   // over S*B*E/4 float4s
    int sb = idx >> 7;                                  // S*B row
    int e4 = (idx & 127) * 4;
    int tok = tokens[sb];
    *(float4*)&g_x[sb * 512 + e4] =
        *(const float4*)&emb[(size_t)tok * 512 + e4];
}

__global__ void init_hidden(const float* __restrict__ src) {
    int i = blockIdx.x * blockDim.x + threadIdx.x;   // 65536 total
    g_hA[i] = src[i];
}

__global__ void copy_hidden(float* __restrict__ dst) {
    int i = blockIdx.x * blockDim.x + threadIdx.x;
    dst[i] = g_hA[i];   // after 64 steps (even # of swaps) current hidden = g_hA
}

// ---------------- GRU gate kernel: r and z, fused GEMM + sigmoid ----------------
// grid = 128 CTAs (8 output columns each over j in [0,1024)), 256 threads.
// Each thread computes 2 outputs (batch pair b0,b0+1 at one column).
__global__ __launch_bounds__(256) void gru_gates(
    int s, int l, int sel,
    const float* __restrict__ Wr, const float* __restrict__ br,
    const float* __restrict__ Wz, const float* __restrict__ bz) {
    const float* hcur = sel ? g_hB : g_hA;
    const float* hnew = sel ? g_hA : g_hB;
    const float* inp  = (l == 0) ? (g_x + s * B_ * E_) : hnew;  // layer1 input = new h0
    const float* hprev = hcur + l * B_ * H_;

    const int j0g = blockIdx.x * 8;        // global gate column base, [0,1024)
    const bool isz = (j0g >= H_);
    const float* W    = isz ? Wz : Wr;     // [1024,512]
    const float* bias = isz ? bz : br;
    const int j0 = isz ? (j0g - H_) : j0g;

    __shared__ __align__(16) float As[64][132];   // row stride 528B: float4-aligned
    __shared__ float Ws[128][8];

    const int tid = threadIdx.x;
    const int col = tid & 7;
    const int b0  = (tid >> 3) * 2;
    float acc0 = 0.f, acc1 = 0.f;

    for (int c = 0; c < 8; ++c) {          // K = 1024 in chunks of 128
        const float* src = (c < 4) ? inp : hprev;
        const int koff = (c & 3) * 128;
        #pragma unroll
        for (int i = 0; i < 8; ++i) {      // stage 64x128 activations
            int idx = tid + i * 256;
            int b = idx >> 5;
            int k4 = (idx & 31) * 4;
            *(float4*)&As[b][k4] = *(const float4*)&src[b * 512 + koff + k4];
        }
        const int kg0 = c * 128;
        #pragma unroll
        for (int i = 0; i < 4; ++i) {      // stage 128x8 weights
            int idx = tid + i * 256;
            int k = idx >> 3, j = idx & 7;
            Ws[k][j] = W[(kg0 + k) * H_ + j0 + j];
        }
        __syncthreads();
        #pragma unroll 16
        for (int k = 0; k < 128; ++k) {
            float w = Ws[k][col];
            acc0 = fmaf(As[b0][k],     w, acc0);
            acc1 = fmaf(As[b0 + 1][k], w, acc1);
        }
        __syncthreads();
    }
    const float bb = bias[j0 + col];
    acc0 += bb; acc1 += bb;
    const int jg = j0g + col;
    g_rz[b0 * K_ + jg]       = 1.f / (1.f + __expf(-acc0));
    g_rz[(b0 + 1) * K_ + jg] = 1.f / (1.f + __expf(-acc1));
}

// ---------------- GRU candidate + state update: fused GEMM + tanh + blend ----------------
// grid = 64 CTAs (8 columns each over j in [0,512)), 256 threads.
__global__ __launch_bounds__(256) void gru_cand(
    int s, int l, int sel,
    const float* __restrict__ Wh, const float* __restrict__ bh) {
    const float* hcur = sel ? g_hB : g_hA;
    float* hnew = sel ? g_hA : g_hB;
    const float* inp  = (l == 0) ? (g_x + s * B_ * E_) : hnew;
    const float* hprev = hcur + l * B_ * H_;
    float* ho = hnew + l * B_ * H_;

    const int j0 = blockIdx.x * 8;
    __shared__ __align__(16) float As[64][132];
    __shared__ float Ws[128][8];
    const int tid = threadIdx.x;
    const int col = tid & 7;
    const int b0  = (tid >> 3) * 2;
    float acc0 = 0.f, acc1 = 0.f;

    for (int c = 0; c < 8; ++c) {
        const int koff = (c & 3) * 128;
        if (c < 4) {
            #pragma unroll
            for (int i = 0; i < 8; ++i) {
                int idx = tid + i * 256;
                int b = idx >> 5;
                int k4 = (idx & 31) * 4;
                *(float4*)&As[b][k4] = *(const float4*)&inp[b * 512 + koff + k4];
            }
        } else {  // second half of cat: r * h_prev
            #pragma unroll
            for (int i = 0; i < 8; ++i) {
                int idx = tid + i * 256;
                int b = idx >> 5;
                int k4 = (idx & 31) * 4;
                float4 hv = *(const float4*)&hprev[b * 512 + koff + k4];
                float4 rv = *(const float4*)&g_rz[b * K_ + koff + k4];
                hv.x *= rv.x; hv.y *= rv.y; hv.z *= rv.z; hv.w *= rv.w;
                *(float4*)&As[b][k4] = hv;
            }
        }
        const int kg0 = c * 128;
        #pragma unroll
        for (int i = 0; i < 4; ++i) {
            int idx = tid + i * 256;
            int k = idx >> 3, j = idx & 7;
            Ws[k][j] = Wh[(kg0 + k) * H_ + j0 + j];
        }
        __syncthreads();
        #pragma unroll 16
        for (int k = 0; k < 128; ++k) {
            float w = Ws[k][col];
            acc0 = fmaf(As[b0][k],     w, acc0);
            acc1 = fmaf(As[b0 + 1][k], w, acc1);
        }
        __syncthreads();
    }
    const int j = j0 + col;
    const float bb = bh[j];
    float hh0 = tanhf(acc0 + bb);
    float hh1 = tanhf(acc1 + bb);
    float z0 = g_rz[b0 * K_ + H_ + j];
    float z1 = g_rz[(b0 + 1) * K_ + H_ + j];
    float h0 = hprev[b0 * 512 + j];
    float h1 = hprev[(b0 + 1) * 512 + j];
    float nh0 = (1.f - z0) * h0 + z0 * hh0;
    float nh1 = (1.f - z1) * h1 + z1 * hh1;
    ho[b0 * 512 + j]       = nh0;
    ho[(b0 + 1) * 512 + j] = nh1;
    if (l == 1) {
        g_hall[s * B_ * H_ + b0 * 512 + j]       = nh0;
        g_hall[s * B_ * H_ + (b0 + 1) * 512 + j] = nh1;
    }
}

// ---------------- Output projection: [4096,512] @ [512,32000] + bias ----------------
// 64x64 tile / CTA, 256 threads, 4x4 micro-tile per thread, packed f32x2 FMAs.
// A duplicated into smem pairs at fill time (so inner loop is pure LDS.64 + FFMA2).
__global__ __launch_bounds__(256) void out_gemm(const float* __restrict__ Wout,
                                                const float* __restrict__ bout,
                                                float* __restrict__ C) {
    __shared__ __align__(16) unsigned long long Asd[16][65];   // duplicated A pairs
    __shared__ __align__(16) float Bs[16][64];

    const int tid = threadIdx.x;
    const int tm = tid >> 4;          // 0..15
    const int tn = tid & 15;          // 0..15
    const int m0 = blockIdx.y * 64;
    const int n0 = blockIdx.x * 64;

    const int la_row = tid >> 2;           // 0..63
    const int la_k   = (tid & 3) * 4;      // 0,4,8,12
    const int lb_k   = tid >> 4;           // 0..15
    const int lb_n   = (tid & 15) * 4;     // 0..60

    unsigned long long acc[4][2];
    #pragma unroll
    for (int i = 0; i < 4; ++i) { acc[i][0] = 0ULL; acc[i][1] = 0ULL; }

    const float* Abase = g_hall + (m0 + la_row) * H_ + la_k;
    const float* Bbase = Wout + (size_t)lb_k * V_ + n0 + lb_n;

    for (int kc = 0; kc < H_ / 16; ++kc) {
        float4 av = *(const float4*)(Abase + kc * 16);
        float4 bv = *(const float4*)(Bbase + (size_t)kc * 16 * V_);
        Asd[la_k + 0][la_row] = pack2(av.x, av.x);
        Asd[la_k + 1][la_row] = pack2(av.y, av.y);
        Asd[la_k + 2][la_row] = pack2(av.z, av.z);
        Asd[la_k + 3][la_row] = pack2(av.w, av.w);
        *(float4*)&Bs[lb_k][lb_n] = bv;
        __syncthreads();
        #pragma unroll
        for (int kk = 0; kk < 16; ++kk) {
            unsigned long long b0 = *(const unsigned long long*)&Bs[kk][2 * tn];
            unsigned long long b1 = *(const unsigned long long*)&Bs[kk][2 * tn + 32];
            #pragma unroll
            for (int i = 0; i < 4; ++i) {
                unsigned long long a = Asd[kk][tm + 16 * i];
                ffma2(acc[i][0], a, b0);
                ffma2(acc[i][1], a, b1);
            }
        }
        __syncthreads();
    }

    float2 bo0 = *(const float2*)&bout[n0 + 2 * tn];
    float2 bo1 = *(const float2*)&bout[n0 + 2 * tn + 32];
    #pragma unroll
    for (int i = 0; i < 4; ++i) {
        int m = m0 + tm + 16 * i;
        float2 v0 = unpack2(acc[i][0]); v0.x += bo0.x; v0.y += bo0.y;
        float2 v1 = unpack2(acc[i][1]); v1.x += bo1.x; v1.y += bo1.y;
        *(float2*)&C[(size_t)m * V_ + n0 + 2 * tn]      = v0;
        *(float2*)&C[(size_t)m * V_ + n0 + 2 * tn + 32] = v1;
    }
}

// ---------------- launch ----------------
extern "C" void kernel_launch(void* const* d_in, const int* in_sizes, int n_in,
                              void* d_out, int out_size) {
    const int*   tokens = (const int*)d_in[0];
    const float* hidden = (const float*)d_in[1];
    const float* emb    = (const float*)d_in[2];
    const float* Wr     = (const float*)d_in[3];
    const float* br     = (const float*)d_in[4];
    const float* Wz     = (const float*)d_in[5];
    const float* bz     = (const float*)d_in[6];
    const float* Wh     = (const float*)d_in[7];
    const float* bh     = (const float*)d_in[8];
    const float* Wout   = (const float*)d_in[9];
    const float* bout   = (const float*)d_in[10];
    float* out = (float*)d_out;

    embed_kernel<<<2048, 256>>>(tokens, emb);   // S*B*E/4 / 256
    init_hidden<<<256, 256>>>(hidden);

    int sel = 0;
    for (int s = 0; s < S_; ++s) {
        for (int l = 0; l < L_; ++l) {
            gru_gates<<<128, 256>>>(s, l, sel,
                                    Wr + l * K_ * H_, br + l * H_,
                                    Wz + l * K_ * H_, bz + l * H_);
            gru_cand<<<64, 256>>>(s, l, sel,
                                  Wh + l * K_ * H_, bh + l * H_);
        }
        sel ^= 1;
    }

    dim3 grid(V_ / 64, (S_ * B_) / 64);   // (500, 64)
    out_gemm<<<grid, 256>>>(Wout, bout, out);

    copy_hidden<<<256, 256>>>(out + (size_t)S_ * B_ * V_);
}